// round 16
// baseline (speedup 1.0000x reference)
#include <cuda_runtime.h>
#include <cuda_fp16.h>
#include <stdint.h>
#include <math.h>

#define B_ 8192
#define D_ 1024
#define H_ 1024
#define K_ 100
#define KGLOB 1024
#define SPLITK 4

// ---------------- device scratch ----------------
__device__ uint4 g_xhi [(size_t)B_ * H_ * 2 / 16];
__device__ uint4 g_h1hi[(size_t)B_ * H_ * 2 / 16];
__device__ uint4 g_h2hi[(size_t)B_ * H_ * 2 / 16];
__device__ uint4 g_w1hi[(size_t)H_ * KGLOB * 2 / 16];
__device__ uint4 g_w2hi[(size_t)H_ * KGLOB * 2 / 16];
__device__ uint4 g_w3hi[(size_t)128 * KGLOB * 2 / 16];
__device__ float4 g_part[(size_t)SPLITK * B_ * 128 / 4];   // GEMM3 partials, row-interleaved

// ---------------- helpers ----------------
__device__ __forceinline__ uint32_t smem_u32(const void* p) {
    uint32_t a;
    asm("{ .reg .u64 t; cvta.to.shared.u64 t, %1; cvt.u32.u64 %0, t; }" : "=r"(a) : "l"(p));
    return a;
}
__device__ __forceinline__ void cp16(uint32_t dst, const void* src) {
    asm volatile("cp.async.cg.shared.global [%0], [%1], 16;" :: "r"(dst), "l"(src));
}
__device__ __forceinline__ void ldsm4(uint32_t* r, uint32_t a) {
    asm volatile("ldmatrix.sync.aligned.m8n8.x4.shared.b16 {%0,%1,%2,%3}, [%4];"
                 : "=r"(r[0]), "=r"(r[1]), "=r"(r[2]), "=r"(r[3]) : "r"(a));
}
__device__ __forceinline__ void ldsm4r(uint32_t& r0, uint32_t& r1, uint32_t& r2, uint32_t& r3,
                                       uint32_t a) {
    asm volatile("ldmatrix.sync.aligned.m8n8.x4.shared.b16 {%0,%1,%2,%3}, [%4];"
                 : "=r"(r0), "=r"(r1), "=r"(r2), "=r"(r3) : "r"(a));
}
__device__ __forceinline__ void mma_f16(float* c, const uint32_t* a, const uint32_t* b) {
    asm volatile("mma.sync.aligned.m16n8k16.row.col.f32.f16.f16.f32 "
                 "{%0,%1,%2,%3},{%4,%5,%6,%7},{%8,%9},{%0,%1,%2,%3};"
                 : "+f"(c[0]), "+f"(c[1]), "+f"(c[2]), "+f"(c[3])
                 : "r"(a[0]), "r"(a[1]), "r"(a[2]), "r"(a[3]), "r"(b[0]), "r"(b[1]));
}

// smem tiles: rows of 32 fp16 (64B) at stride 80B -> 16B-aligned, conflict-free ldmatrix
#define RSTRIDE 80u
#define ATILEB  5120u          // 64 rows * 80
#define BTILEB  10240u         // 128 rows * 80
#define STGB    15360u         // A tile + B tile
#define NSTG    3

// per stage: A 64 rows x 64B, B 128 rows x 64B. 256 threads.
__device__ __forceinline__ void issue_stage(
    uint32_t sbase, int stg,
    const __half* gA, const __half* gB, int kt, int tid)
{
    const uint32_t sb = sbase + (uint32_t)stg * STGB;
    {
        const int row = tid >> 1, seg = tid & 1;
        const uint32_t db = sb + ATILEB + (uint32_t)row * RSTRIDE + (uint32_t)seg * 32u;
        const size_t go = (size_t)row * KGLOB + (size_t)kt * 32 + (size_t)seg * 16;
        cp16(db,       gB + go);
        cp16(db + 16u, gB + go + 8);
    }
    {
        const int row = tid >> 2, seg = tid & 3;
        const uint32_t da = sb + (uint32_t)row * RSTRIDE + (uint32_t)seg * 16u;
        const size_t ga = (size_t)row * KGLOB + (size_t)kt * 32 + (size_t)seg * 8;
        cp16(da, gA + ga);
    }
    asm volatile("cp.async.commit_group;" ::: "memory");
}

// ---------------- fp16 tensor-core GEMM: out = act(A @ B^T + bias) ----------------
// CTA 64x128, 8 warps (2m x 4n) each 32x32, BK=32, 3-stage, occ 4 (32 warps/SM, RF-full).
__global__ __launch_bounds__(256, 4)
void gemm_mma(const __half* __restrict__ A, const __half* __restrict__ Bw,
              const float* __restrict__ bias, float* __restrict__ C,
              __half* __restrict__ Chi,
              int Nout, int ldC, int doSilu, int splitOut, int kIters, size_t partOff)
{
    extern __shared__ __align__(128) char smraw[];
    const uint32_t sbase = smem_u32(smraw);
    const int tid = threadIdx.x, lane = tid & 31, wid = tid >> 5;
    const int warpRow = wid >> 2, warpCol = wid & 3;      // 2 x 4
    const int rowA = blockIdx.y * 64, rowB = blockIdx.x * 128;
    const int kOff = blockIdx.z * kIters;
    if (partOff) C += (size_t)blockIdx.z * partOff;

    const __half* gA = A  + (size_t)rowA * KGLOB;
    const __half* gB = Bw + (size_t)rowB * KGLOB;

    float acc[2][4][4];
#pragma unroll
    for (int mt = 0; mt < 2; mt++)
#pragma unroll
        for (int nt = 0; nt < 4; nt++)
#pragma unroll
            for (int i = 0; i < 4; i++) acc[mt][nt][i] = 0.f;

    issue_stage(sbase, 0, gA, gB, kOff, tid);
    issue_stage(sbase, 1, gA, gB, kOff + 1, tid);

    const uint32_t aoff_c = (uint32_t)warpRow * (32u * RSTRIDE)
                          + (uint32_t)(lane & 15) * RSTRIDE + (uint32_t)(lane >> 4) * 16u;
    const uint32_t bn = (uint32_t)((lane & 7) | ((lane >> 4) << 3));
    const uint32_t boff_c = ((uint32_t)warpCol * 32u + bn) * RSTRIDE + (uint32_t)((lane >> 3) & 1) * 16u;

#pragma unroll 1
    for (int tt = 0; tt < kIters; tt++) {
        asm volatile("cp.async.wait_group 1;" ::: "memory");
        __syncthreads();
        if (tt + 2 < kIters) issue_stage(sbase, (tt + 2) % NSTG, gA, gB, kOff + tt + 2, tid);
        else asm volatile("cp.async.commit_group;" ::: "memory");

        const uint32_t cb = sbase + (uint32_t)(tt % NSTG) * STGB;
#pragma unroll
        for (int s = 0; s < 2; s++) {
            uint32_t ah[2][4], bh[4][2];
            const uint32_t ao = cb + aoff_c + (uint32_t)s * 32u;
#pragma unroll
            for (int mt = 0; mt < 2; mt++) ldsm4(ah[mt], ao + (uint32_t)mt * (16u * RSTRIDE));
            const uint32_t bo = cb + ATILEB + boff_c + (uint32_t)s * 32u;
            ldsm4r(bh[0][0], bh[0][1], bh[1][0], bh[1][1], bo);
            ldsm4r(bh[2][0], bh[2][1], bh[3][0], bh[3][1], bo + 16u * RSTRIDE);
#pragma unroll
            for (int mt = 0; mt < 2; mt++)
#pragma unroll
                for (int nt = 0; nt < 4; nt++)
                    mma_f16(acc[mt][nt], ah[mt], bh[nt]);
        }
    }

    // epilogue
#pragma unroll
    for (int mt = 0; mt < 2; mt++) {
        const int row0 = rowA + warpRow * 32 + mt * 16 + (lane >> 2);
#pragma unroll
        for (int nt = 0; nt < 4; nt++) {
            const int col = blockIdx.x * 128 + warpCol * 32 + nt * 8 + (lane & 3) * 2;
            if (col < Nout) {
                const float bx = bias ? bias[col] : 0.f;
                const float by = bias ? bias[col + 1] : 0.f;
                float2 v0, v1;
                v0.x = acc[mt][nt][0] + bx; v0.y = acc[mt][nt][1] + by;
                v1.x = acc[mt][nt][2] + bx; v1.y = acc[mt][nt][3] + by;
                if (doSilu) {
                    v0.x = v0.x / (1.f + __expf(-v0.x));
                    v0.y = v0.y / (1.f + __expf(-v0.y));
                    v1.x = v1.x / (1.f + __expf(-v1.x));
                    v1.y = v1.y / (1.f + __expf(-v1.y));
                }
                if (splitOut) {
                    const size_t o0 = (size_t)row0 * KGLOB + col;
                    const size_t o1 = (size_t)(row0 + 8) * KGLOB + col;
                    *(__half2*)(Chi + o0) = __halves2half2(__float2half(v0.x), __float2half(v0.y));
                    *(__half2*)(Chi + o1) = __halves2half2(__float2half(v1.x), __float2half(v1.y));
                } else {
                    *(float2*)&C[(size_t)row0 * ldC + col] = v0;
                    *(float2*)&C[(size_t)(row0 + 8) * ldC + col] = v1;
                }
            }
        }
    }
}

// ---------------- fused prep: W1/W2/W3 transpose->fp16 + x->fp16 ----------------
// blockIdx.z: 0 = W1, 1 = W2, 2 = W3, 3 = x convert. 256 threads.
__global__ void prep_kernel(const float* __restrict__ W1, const float* __restrict__ W2,
                            const float* __restrict__ W3, const float* __restrict__ x,
                            __half* __restrict__ T1, __half* __restrict__ T2,
                            __half* __restrict__ T3, __half2* __restrict__ xh)
{
    const int seg = blockIdx.z;
    if (seg == 3) {
        // x convert: 256*32 = 8192 blocks cover B_*H_/4 float4 elems
        const size_t i = ((size_t)blockIdx.y * gridDim.x + blockIdx.x) * 256 + threadIdx.x;
        if (i < (size_t)B_ * H_ / 4) {
            float4 v = ((const float4*)x)[i];
            xh[2 * i]     = __halves2half2(__float2half(v.x), __float2half(v.y));
            xh[2 * i + 1] = __halves2half2(__float2half(v.z), __float2half(v.w));
        }
        return;
    }
    // weight transposes: W1/W2 need blockIdx.x < 32, W3 < 4; guard ALL segments
    if (seg <  2 && blockIdx.x >= 32) return;
    if (seg == 2 && blockIdx.x >= 4)  return;

    const float* W = (seg == 0) ? W1 : (seg == 1) ? W2 : W3;
    __half* T      = (seg == 0) ? T1 : (seg == 1) ? T2 : T3;
    const int N    = (seg == 2) ? K_ : H_;

    __shared__ float tile[32][33];
    const int n0 = blockIdx.x * 32, k0 = blockIdx.y * 32;
    const int tx = threadIdx.x & 31, ty = threadIdx.x >> 5;
#pragma unroll
    for (int i = 0; i < 4; i++) {
        const int k = k0 + ty + i * 8, n = n0 + tx;
        tile[ty + i * 8][tx] = (n < N) ? W[(size_t)k * N + n] : 0.0f;
    }
    __syncthreads();
#pragma unroll
    for (int i = 0; i < 4; i++) {
        const int n = n0 + ty + i * 8, k = k0 + tx;
        T[(size_t)n * KGLOB + k] = __float2half(tile[tx][ty + i * 8]);
    }
}

// ---------------- reductions ----------------
__device__ __forceinline__ float warpSum(float v) {
#pragma unroll
    for (int o = 16; o > 0; o >>= 1) v += __shfl_down_sync(0xffffffffu, v, o);
    return v;
}
__device__ __forceinline__ float blockSum(float v, float* sm, int nwarps) {
    int lane = threadIdx.x & 31, w = threadIdx.x >> 5;
    v = warpSum(v);
    __syncthreads();
    if (lane == 0) sm[w] = v;
    __syncthreads();
    if (w == 0) {
        float x = (lane < nwarps) ? sm[lane] : 0.f;
        x = warpSum(x);
        if (lane == 0) sm[0] = x;
    }
    __syncthreads();
    return sm[0];
}

// ---------------- LayerNorm in place on fp16 buffer ----------------
__global__ void layernorm_inplace_kernel(__half2* __restrict__ h, const float* __restrict__ g,
                                         const float* __restrict__ beta)
{
    __shared__ float sred[8];
    const int row = blockIdx.x;
    __half2* r = h + (size_t)row * (H_ / 2);
    const int t2 = threadIdx.x * 2;
    __half2 a = r[t2], b = r[t2 + 1];
    float2 fa = __half22float2(a), fb = __half22float2(b);
    float s = fa.x + fa.y + fb.x + fb.y;
    s = blockSum(s, sred, 8);
    const float mu = s * (1.0f / H_);
    const float dx = fa.x - mu, dy = fa.y - mu, dz = fb.x - mu, dw = fb.y - mu;
    float q = dx * dx + dy * dy + dz * dz + dw * dw;
    q = blockSum(q, sred, 8);
    const float rsig = rsqrtf(q * (1.0f / H_) + 1e-5f);
    const int c = threadIdx.x * 4;
    const float ox = dx * rsig * g[c + 0] + beta[c + 0];
    const float oy = dy * rsig * g[c + 1] + beta[c + 1];
    const float oz = dz * rsig * g[c + 2] + beta[c + 2];
    const float ow = dw * rsig * g[c + 3] + beta[c + 3];
    r[t2]     = __halves2half2(__float2half(ox), __float2half(oy));
    r[t2 + 1] = __halves2half2(__float2half(oz), __float2half(ow));
}

// ---------------- evidential head (contiguous interleaved partials) ----------------
__device__ __forceinline__ float softplusf(float x) {
    return fmaxf(x, 0.f) + log1pf(__expf(-fabsf(x)));
}
__device__ __forceinline__ float digammaf_(float x) {
    float r = 0.f;
#pragma unroll
    for (int i = 0; i < 5; i++) {
        if (x < 6.f) { r -= __fdividef(1.f, x); x += 1.f; }
    }
    const float inv = __fdividef(1.f, x);
    const float inv2 = inv * inv;
    const float ser = inv2 * (0.0833333333f - inv2 * (0.0083333333f - inv2 * 0.0039682540f));
    return r + logf(x) - 0.5f * inv - ser;
}

__global__ void head_kernel(const float* __restrict__ partial, const float* __restrict__ b3,
                            float* __restrict__ alpha_o, float* __restrict__ evid_o,
                            float* __restrict__ eprob_o, float* __restrict__ vac_o,
                            float* __restrict__ diss_o, float* __restrict__ alea_o)
{
    __shared__ float sb[K_];
    __shared__ float sa[K_];
    __shared__ float sm[4];
    const int row = blockIdx.x;
    const int t = threadIdx.x;

    float e = 0.f, a = 0.f;
    if (t < K_) {
        float xv = b3[t];
        const float* pp = partial + (size_t)row * (SPLITK * 128) + t;
#pragma unroll
        for (int c = 0; c < SPLITK; c++) xv += pp[c * 128];
        e = softplusf(xv);
        a = e + 1.f;
    }
    const float S = blockSum(a, sm, 4);

    if (t < K_) {
        const size_t o = (size_t)row * K_ + t;
        alpha_o[o] = a;
        evid_o[o] = e;
        eprob_o[o] = a / S;
        sb[t] = e / S;
        sa[t] = a;
    }
    if (t == 0) vac_o[row] = (float)K_ / S;
    __syncthreads();

    float pairsum = 0.f;
    for (int idx = t; idx < K_ * K_; idx += 128) {
        const int i = idx / K_;
        const int j = idx - i * K_;
        if (i < j) {
            const float bi = sb[i], bj = sb[j];
            const float den = bi + bj + 1e-8f;
            pairsum += (1.f - __fdividef(fabsf(bi - bj), den)) * bi * bj;
        }
    }
    pairsum = blockSum(pairsum, sm, 4);

    const float psiS = digammaf_(S);
    float al = 0.f;
    if (t < K_) al = (sa[t] / S) * (digammaf_(sa[t]) - psiS);
    const float alea = blockSum(al, sm, 4);

    if (t == 0) {
        diss_o[row] = pairsum;
        alea_o[row] = -alea;
    }
}

// ---------------- launch ----------------
extern "C" void kernel_launch(void* const* d_in, const int* in_sizes, int n_in,
                              void* d_out, int out_size)
{
    const float* x    = (const float*)d_in[0];
    const float* W1   = (const float*)d_in[1];
    const float* b1   = (const float*)d_in[2];
    const float* g    = (const float*)d_in[3];
    const float* beta = (const float*)d_in[4];
    const float* W2   = (const float*)d_in[5];
    const float* b2   = (const float*)d_in[6];
    const float* W3   = (const float*)d_in[7];
    const float* b3   = (const float*)d_in[8];

    void *p;
    cudaGetSymbolAddress(&p, g_xhi);  __half* xhi  = (__half*)p;
    cudaGetSymbolAddress(&p, g_h1hi); __half* h1hi = (__half*)p;
    cudaGetSymbolAddress(&p, g_h2hi); __half* h2hi = (__half*)p;
    cudaGetSymbolAddress(&p, g_w1hi); __half* w1hi = (__half*)p;
    cudaGetSymbolAddress(&p, g_w2hi); __half* w2hi = (__half*)p;
    cudaGetSymbolAddress(&p, g_w3hi); __half* w3hi = (__half*)p;
    cudaGetSymbolAddress(&p, g_part); float* part = (float*)p;

    const int DSMEM = NSTG * (int)STGB;   // 46080
    cudaFuncSetAttribute(gemm_mma, cudaFuncAttributeMaxDynamicSharedMemorySize, DSMEM);

    // fused prep: z=0..2 weight transposes (guarded), z=3 x convert
    prep_kernel<<<dim3(256, 32, 4), 256>>>(W1, W2, W3, x, w1hi, w2hi, w3hi, (__half2*)xhi);

    // GEMM1 + silu -> fp16 h1
    gemm_mma<<<dim3(8, 128, 1), 256, DSMEM>>>(xhi, w1hi, b1, nullptr, h1hi,
                                              H_, H_, 1, 1, 32, 0);
    // LayerNorm in place
    layernorm_inplace_kernel<<<B_, 256>>>((__half2*)h1hi, g, beta);
    // GEMM2 + silu -> fp16 h2
    gemm_mma<<<dim3(8, 128, 1), 256, DSMEM>>>(h1hi, w2hi, b2, nullptr, h2hi,
                                              H_, H_, 1, 1, 32, 0);
    // GEMM3 split-K=4 -> interleaved partials: part[row*512 + z*128 + col], 512 CTAs = 1 wave
    gemm_mma<<<dim3(1, 128, SPLITK), 256, DSMEM>>>(h2hi, w3hi, nullptr, part, nullptr,
                                                   128, SPLITK * 128, 0, 0,
                                                   32 / SPLITK, 128);

    float* out = (float*)d_out;
    const size_t BK = (size_t)B_ * K_;
    head_kernel<<<B_, 128>>>(part, b3,
                             out,                    // alpha
                             out + BK,               // evidence
                             out + 2 * BK,           // expected_prob
                             out + 3 * BK,           // vacuity
                             out + 3 * BK + B_,      // dissonance
                             out + 3 * BK + 2 * B_); // aleatoric
}

// round 17
// speedup vs baseline: 1.0368x; 1.0368x over previous
#include <cuda_runtime.h>
#include <cuda_fp16.h>
#include <stdint.h>
#include <math.h>

#define B_ 8192
#define D_ 1024
#define H_ 1024
#define K_ 100
#define KGLOB 1024
#define SPLITK 8

// ---------------- device scratch ----------------
__device__ uint4 g_xhi [(size_t)B_ * H_ * 2 / 16];
__device__ uint4 g_h1hi[(size_t)B_ * H_ * 2 / 16];
__device__ uint4 g_h2hi[(size_t)B_ * H_ * 2 / 16];
__device__ uint4 g_w1hi[(size_t)H_ * KGLOB * 2 / 16];
__device__ uint4 g_w2hi[(size_t)H_ * KGLOB * 2 / 16];
__device__ uint4 g_w3hi[(size_t)128 * KGLOB * 2 / 16];
__device__ float4 g_part[(size_t)SPLITK * B_ * 128 / 4];   // GEMM3 partials, row-interleaved

// ---------------- helpers ----------------
__device__ __forceinline__ uint32_t smem_u32(const void* p) {
    uint32_t a;
    asm("{ .reg .u64 t; cvta.to.shared.u64 t, %1; cvt.u32.u64 %0, t; }" : "=r"(a) : "l"(p));
    return a;
}
__device__ __forceinline__ void cp16(uint32_t dst, const void* src) {
    asm volatile("cp.async.cg.shared.global [%0], [%1], 16;" :: "r"(dst), "l"(src));
}
__device__ __forceinline__ void ldsm4(uint32_t* r, uint32_t a) {
    asm volatile("ldmatrix.sync.aligned.m8n8.x4.shared.b16 {%0,%1,%2,%3}, [%4];"
                 : "=r"(r[0]), "=r"(r[1]), "=r"(r[2]), "=r"(r[3]) : "r"(a));
}
__device__ __forceinline__ void ldsm4r(uint32_t& r0, uint32_t& r1, uint32_t& r2, uint32_t& r3,
                                       uint32_t a) {
    asm volatile("ldmatrix.sync.aligned.m8n8.x4.shared.b16 {%0,%1,%2,%3}, [%4];"
                 : "=r"(r0), "=r"(r1), "=r"(r2), "=r"(r3) : "r"(a));
}
__device__ __forceinline__ void mma_f16(float* c, const uint32_t* a, const uint32_t* b) {
    asm volatile("mma.sync.aligned.m16n8k16.row.col.f32.f16.f16.f32 "
                 "{%0,%1,%2,%3},{%4,%5,%6,%7},{%8,%9},{%0,%1,%2,%3};"
                 : "+f"(c[0]), "+f"(c[1]), "+f"(c[2]), "+f"(c[3])
                 : "r"(a[0]), "r"(a[1]), "r"(a[2]), "r"(a[3]), "r"(b[0]), "r"(b[1]));
}

// smem tiles: rows of 32 fp16 (64B) at stride 80B -> 16B-aligned, conflict-free ldmatrix
#define RSTRIDE 80u
#define ATILEB  5120u          // 64 rows * 80
#define BTILEB  10240u         // 128 rows * 80
#define STGB    15360u         // A tile + B tile
#define NSTG    3

// loader with pre-offset global pointers (caller advances gA/gB by 32 per stage)
__device__ __forceinline__ void issue_stage_p(
    uint32_t sb, const __half* gAk, const __half* gBk,
    uint32_t dbB, uint32_t daA, size_t goB, size_t gaA)
{
    cp16(sb + dbB,       gBk + goB);
    cp16(sb + dbB + 16u, gBk + goB + 8);
    cp16(sb + daA,       gAk + gaA);
    asm volatile("cp.async.commit_group;" ::: "memory");
}

// ---------------- fp16 tensor-core GEMM: out = act(A @ B^T + bias) ----------------
// CTA 64x128, 8 warps (2m x 4n) each 32x32, BK=32, 3-stage, occ 4 (32 warps/SM, RF-full).
__global__ __launch_bounds__(256, 4)
void gemm_mma(const __half* __restrict__ A, const __half* __restrict__ Bw,
              const float* __restrict__ bias, float* __restrict__ C,
              __half* __restrict__ Chi,
              int Nout, int ldC, int doSilu, int splitOut, int kIters, size_t partOff)
{
    extern __shared__ __align__(128) char smraw[];
    const uint32_t sbase = smem_u32(smraw);
    const int tid = threadIdx.x, lane = tid & 31, wid = tid >> 5;
    const int warpRow = wid >> 2, warpCol = wid & 3;      // 2 x 4
    const int rowA = blockIdx.y * 64, rowB = blockIdx.x * 128;
    if (partOff) C += (size_t)blockIdx.z * partOff;

    // hoisted per-thread loader constants
    const uint32_t dbB = ATILEB + (uint32_t)(tid >> 1) * RSTRIDE + (uint32_t)(tid & 1) * 32u;
    const size_t   goB = (size_t)(tid >> 1) * KGLOB + (size_t)(tid & 1) * 16;
    const uint32_t daA = (uint32_t)(tid >> 2) * RSTRIDE + (uint32_t)(tid & 3) * 16u;
    const size_t   gaA = (size_t)(tid >> 2) * KGLOB + (size_t)(tid & 3) * 8;

    // global pointers, advanced 32 halves per stage
    const __half* gAk = A  + (size_t)rowA * KGLOB + (size_t)blockIdx.z * kIters * 32;
    const __half* gBk = Bw + (size_t)rowB * KGLOB + (size_t)blockIdx.z * kIters * 32;

    float acc[2][4][4];
#pragma unroll
    for (int mt = 0; mt < 2; mt++)
#pragma unroll
        for (int nt = 0; nt < 4; nt++)
#pragma unroll
            for (int i = 0; i < 4; i++) acc[mt][nt][i] = 0.f;

    issue_stage_p(sbase, gAk, gBk, dbB, daA, goB, gaA);           gAk += 32; gBk += 32;
    issue_stage_p(sbase + STGB, gAk, gBk, dbB, daA, goB, gaA);    gAk += 32; gBk += 32;

    const uint32_t aoff_c = (uint32_t)warpRow * (32u * RSTRIDE)
                          + (uint32_t)(lane & 15) * RSTRIDE + (uint32_t)(lane >> 4) * 16u;
    const uint32_t bn = (uint32_t)((lane & 7) | ((lane >> 4) << 3));
    const uint32_t boff_c = ((uint32_t)warpCol * 32u + bn) * RSTRIDE + (uint32_t)((lane >> 3) & 1) * 16u;

    uint32_t rd_off = 0u;               // stage being consumed
    uint32_t wr_off = 2u * STGB;        // stage being filled

#pragma unroll 1
    for (int tt = 0; tt < kIters; tt++) {
        asm volatile("cp.async.wait_group 1;" ::: "memory");
        __syncthreads();
        if (tt + 2 < kIters) {
            issue_stage_p(sbase + wr_off, gAk, gBk, dbB, daA, goB, gaA);
            gAk += 32; gBk += 32;
            wr_off = (wr_off == 2u * STGB) ? 0u : wr_off + STGB;
        } else {
            asm volatile("cp.async.commit_group;" ::: "memory");
        }

        const uint32_t cb = sbase + rd_off;
        rd_off = (rd_off == 2u * STGB) ? 0u : rd_off + STGB;
#pragma unroll
        for (int s = 0; s < 2; s++) {
            uint32_t ah[2][4], bh[4][2];
            const uint32_t ao = cb + aoff_c + (uint32_t)s * 32u;
#pragma unroll
            for (int mt = 0; mt < 2; mt++) ldsm4(ah[mt], ao + (uint32_t)mt * (16u * RSTRIDE));
            const uint32_t bo = cb + ATILEB + boff_c + (uint32_t)s * 32u;
            ldsm4r(bh[0][0], bh[0][1], bh[1][0], bh[1][1], bo);
            ldsm4r(bh[2][0], bh[2][1], bh[3][0], bh[3][1], bo + 16u * RSTRIDE);
#pragma unroll
            for (int mt = 0; mt < 2; mt++)
#pragma unroll
                for (int nt = 0; nt < 4; nt++)
                    mma_f16(acc[mt][nt], ah[mt], bh[nt]);
        }
    }

    // epilogue
#pragma unroll
    for (int mt = 0; mt < 2; mt++) {
        const int row0 = rowA + warpRow * 32 + mt * 16 + (lane >> 2);
#pragma unroll
        for (int nt = 0; nt < 4; nt++) {
            const int col = blockIdx.x * 128 + warpCol * 32 + nt * 8 + (lane & 3) * 2;
            if (col < Nout) {
                const float bx = bias ? bias[col] : 0.f;
                const float by = bias ? bias[col + 1] : 0.f;
                float2 v0, v1;
                v0.x = acc[mt][nt][0] + bx; v0.y = acc[mt][nt][1] + by;
                v1.x = acc[mt][nt][2] + bx; v1.y = acc[mt][nt][3] + by;
                if (doSilu) {
                    v0.x = v0.x / (1.f + __expf(-v0.x));
                    v0.y = v0.y / (1.f + __expf(-v0.y));
                    v1.x = v1.x / (1.f + __expf(-v1.x));
                    v1.y = v1.y / (1.f + __expf(-v1.y));
                }
                if (splitOut) {
                    const size_t o0 = (size_t)row0 * KGLOB + col;
                    const size_t o1 = (size_t)(row0 + 8) * KGLOB + col;
                    *(__half2*)(Chi + o0) = __halves2half2(__float2half(v0.x), __float2half(v0.y));
                    *(__half2*)(Chi + o1) = __halves2half2(__float2half(v1.x), __float2half(v1.y));
                } else {
                    *(float2*)&C[(size_t)row0 * ldC + col] = v0;
                    *(float2*)&C[(size_t)(row0 + 8) * ldC + col] = v1;
                }
            }
        }
    }
}

// ---------------- fp32 -> fp16 (input x) ----------------
__global__ void split_kernel(const float4* __restrict__ src, __half2* __restrict__ hi)
{
    const size_t i = (size_t)blockIdx.x * 256 + threadIdx.x;
    float4 v = src[i];
    hi[2 * i]     = __halves2half2(__float2half(v.x), __float2half(v.y));
    hi[2 * i + 1] = __halves2half2(__float2half(v.z), __float2half(v.w));
}

// ---------------- W [K,N] fp32 -> transposed [Npad,K] fp16 ----------------
__global__ void transpose_hi(const float* __restrict__ W, __half* __restrict__ T, int N)
{
    __shared__ float tile[32][33];
    const int n0 = blockIdx.x * 32, k0 = blockIdx.y * 32;
    const int tx = threadIdx.x, ty = threadIdx.y;
#pragma unroll
    for (int i = 0; i < 4; i++) {
        const int k = k0 + ty + i * 8, n = n0 + tx;
        tile[ty + i * 8][tx] = (n < N) ? W[(size_t)k * N + n] : 0.0f;
    }
    __syncthreads();
#pragma unroll
    for (int i = 0; i < 4; i++) {
        const int n = n0 + ty + i * 8, k = k0 + tx;
        T[(size_t)n * KGLOB + k] = __float2half(tile[tx][ty + i * 8]);
    }
}

// ---------------- reductions ----------------
__device__ __forceinline__ float warpSum(float v) {
#pragma unroll
    for (int o = 16; o > 0; o >>= 1) v += __shfl_down_sync(0xffffffffu, v, o);
    return v;
}
__device__ __forceinline__ float blockSum(float v, float* sm, int nwarps) {
    int lane = threadIdx.x & 31, w = threadIdx.x >> 5;
    v = warpSum(v);
    __syncthreads();
    if (lane == 0) sm[w] = v;
    __syncthreads();
    if (w == 0) {
        float x = (lane < nwarps) ? sm[lane] : 0.f;
        x = warpSum(x);
        if (lane == 0) sm[0] = x;
    }
    __syncthreads();
    return sm[0];
}

// ---------------- LayerNorm in place on fp16 buffer ----------------
__global__ void layernorm_inplace_kernel(__half2* __restrict__ h, const float* __restrict__ g,
                                         const float* __restrict__ beta)
{
    __shared__ float sred[8];
    const int row = blockIdx.x;
    __half2* r = h + (size_t)row * (H_ / 2);
    const int t2 = threadIdx.x * 2;
    __half2 a = r[t2], b = r[t2 + 1];
    float2 fa = __half22float2(a), fb = __half22float2(b);
    float s = fa.x + fa.y + fb.x + fb.y;
    s = blockSum(s, sred, 8);
    const float mu = s * (1.0f / H_);
    const float dx = fa.x - mu, dy = fa.y - mu, dz = fb.x - mu, dw = fb.y - mu;
    float q = dx * dx + dy * dy + dz * dz + dw * dw;
    q = blockSum(q, sred, 8);
    const float rsig = rsqrtf(q * (1.0f / H_) + 1e-5f);
    const int c = threadIdx.x * 4;
    const float ox = dx * rsig * g[c + 0] + beta[c + 0];
    const float oy = dy * rsig * g[c + 1] + beta[c + 1];
    const float oz = dz * rsig * g[c + 2] + beta[c + 2];
    const float ow = dw * rsig * g[c + 3] + beta[c + 3];
    r[t2]     = __halves2half2(__float2half(ox), __float2half(oy));
    r[t2 + 1] = __halves2half2(__float2half(oz), __float2half(ow));
}

// ---------------- evidential head (contiguous interleaved partials) ----------------
__device__ __forceinline__ float softplusf(float x) {
    return fmaxf(x, 0.f) + log1pf(__expf(-fabsf(x)));
}
__device__ __forceinline__ float digammaf_(float x) {
    float r = 0.f;
#pragma unroll
    for (int i = 0; i < 5; i++) {
        if (x < 6.f) { r -= __fdividef(1.f, x); x += 1.f; }
    }
    const float inv = __fdividef(1.f, x);
    const float inv2 = inv * inv;
    const float ser = inv2 * (0.0833333333f - inv2 * (0.0083333333f - inv2 * 0.0039682540f));
    return r + logf(x) - 0.5f * inv - ser;
}

__global__ void head_kernel(const float* __restrict__ partial, const float* __restrict__ b3,
                            float* __restrict__ alpha_o, float* __restrict__ evid_o,
                            float* __restrict__ eprob_o, float* __restrict__ vac_o,
                            float* __restrict__ diss_o, float* __restrict__ alea_o)
{
    __shared__ float sb[K_];
    __shared__ float sa[K_];
    __shared__ float sm[4];
    const int row = blockIdx.x;
    const int t = threadIdx.x;

    float e = 0.f, a = 0.f;
    if (t < K_) {
        float xv = b3[t];
        const float* pp = partial + (size_t)row * (SPLITK * 128) + t;
#pragma unroll
        for (int c = 0; c < SPLITK; c++) xv += pp[c * 128];
        e = softplusf(xv);
        a = e + 1.f;
    }
    const float S = blockSum(a, sm, 4);

    if (t < K_) {
        const size_t o = (size_t)row * K_ + t;
        alpha_o[o] = a;
        evid_o[o] = e;
        eprob_o[o] = a / S;
        sb[t] = e / S;
        sa[t] = a;
    }
    if (t == 0) vac_o[row] = (float)K_ / S;
    __syncthreads();

    float pairsum = 0.f;
    for (int idx = t; idx < K_ * K_; idx += 128) {
        const int i = idx / K_;
        const int j = idx - i * K_;
        if (i < j) {
            const float bi = sb[i], bj = sb[j];
            const float den = bi + bj + 1e-8f;
            pairsum += (1.f - __fdividef(fabsf(bi - bj), den)) * bi * bj;
        }
    }
    pairsum = blockSum(pairsum, sm, 4);

    const float psiS = digammaf_(S);
    float al = 0.f;
    if (t < K_) al = (sa[t] / S) * (digammaf_(sa[t]) - psiS);
    const float alea = blockSum(al, sm, 4);

    if (t == 0) {
        diss_o[row] = pairsum;
        alea_o[row] = -alea;
    }
}

// ---------------- launch ----------------
extern "C" void kernel_launch(void* const* d_in, const int* in_sizes, int n_in,
                              void* d_out, int out_size)
{
    const float* x    = (const float*)d_in[0];
    const float* W1   = (const float*)d_in[1];
    const float* b1   = (const float*)d_in[2];
    const float* g    = (const float*)d_in[3];
    const float* beta = (const float*)d_in[4];
    const float* W2   = (const float*)d_in[5];
    const float* b2   = (const float*)d_in[6];
    const float* W3   = (const float*)d_in[7];
    const float* b3   = (const float*)d_in[8];

    void *p;
    cudaGetSymbolAddress(&p, g_xhi);  __half* xhi  = (__half*)p;
    cudaGetSymbolAddress(&p, g_h1hi); __half* h1hi = (__half*)p;
    cudaGetSymbolAddress(&p, g_h2hi); __half* h2hi = (__half*)p;
    cudaGetSymbolAddress(&p, g_w1hi); __half* w1hi = (__half*)p;
    cudaGetSymbolAddress(&p, g_w2hi); __half* w2hi = (__half*)p;
    cudaGetSymbolAddress(&p, g_w3hi); __half* w3hi = (__half*)p;
    cudaGetSymbolAddress(&p, g_part); float* part = (float*)p;

    const int DSMEM = NSTG * (int)STGB;   // 46080
    cudaFuncSetAttribute(gemm_mma, cudaFuncAttributeMaxDynamicSharedMemorySize, DSMEM);

    const int splitBlocks = (B_ * H_) / 4 / 256;   // 8192

    transpose_hi<<<dim3(32, 32), dim3(32, 8)>>>(W1, w1hi, H_);
    transpose_hi<<<dim3(32, 32), dim3(32, 8)>>>(W2, w2hi, H_);
    transpose_hi<<<dim3(4, 32),  dim3(32, 8)>>>(W3, w3hi, K_);

    split_kernel<<<splitBlocks, 256>>>((const float4*)x, (__half2*)xhi);

    // GEMM1 + silu -> fp16 h1
    gemm_mma<<<dim3(8, 128, 1), 256, DSMEM>>>(xhi, w1hi, b1, nullptr, h1hi,
                                              H_, H_, 1, 1, 32, 0);
    // LayerNorm in place
    layernorm_inplace_kernel<<<B_, 256>>>((__half2*)h1hi, g, beta);
    // GEMM2 + silu -> fp16 h2
    gemm_mma<<<dim3(8, 128, 1), 256, DSMEM>>>(h1hi, w2hi, b2, nullptr, h2hi,
                                              H_, H_, 1, 1, 32, 0);
    // GEMM3 split-K=8 -> interleaved partials: part[row*1024 + z*128 + col]
    gemm_mma<<<dim3(1, 128, SPLITK), 256, DSMEM>>>(h2hi, w3hi, nullptr, part, nullptr,
                                                   128, SPLITK * 128, 0, 0,
                                                   32 / SPLITK, 128);

    float* out = (float*)d_out;
    const size_t BK = (size_t)B_ * K_;
    head_kernel<<<B_, 128>>>(part, b3,
                             out,                    // alpha
                             out + BK,               // evidence
                             out + 2 * BK,           // expected_prob
                             out + 3 * BK,           // vacuity
                             out + 3 * BK + B_,      // dissonance
                             out + 3 * BK + 2 * B_); // aleatoric
}